// round 14
// baseline (speedup 1.0000x reference)
#include <cuda_runtime.h>
#include <math.h>

#define V 32000
#define EDIM 256
#define HDIM 128
#define BB 64
#define SS 1024
#define TT 4

typedef unsigned long long ull;

// ---------------- scratch (static device globals) ---------------------------
__device__ float g_table[V * 1024];     // [v][dir*512 + g] : PURE x@W_ih.T
__device__ float g_h[SS * BB * 256];    // [s][b][dir*128 + j]
__device__ float g_feats[BB * SS * TT]; // [b][s][t]
__device__ int   g_dummy;

// ---------------- packed f32x2 helpers --------------------------------------
__device__ __forceinline__ void fma2(ull &acc, ull a, ull b) {
    asm("fma.rn.f32x2 %0, %1, %2, %0;" : "+l"(acc) : "l"(a), "l"(b));
}
__device__ __forceinline__ ull pack2(float lo, float hi) {
    ull r; asm("mov.b64 %0, {%1, %2};" : "=l"(r) : "f"(lo), "f"(hi)); return r;
}
__device__ __forceinline__ void unpack2(ull v, float &lo, float &hi) {
    asm("mov.b64 {%0, %1}, %2;" : "=f"(lo), "=f"(hi) : "l"(v));
}

// ---------------- XLA-GPU exact nonlinearities ------------------------------
__device__ __forceinline__ float tanh_xla(float x) {
    float ax = fabsf(x);
    float xc = fminf(fmaxf(x, -7.90531110763549805f), 7.90531110763549805f);
    float x2 = __fmul_rn(xc, xc);
    float p = __fmaf_rn(x2, -2.76076847742355e-16f, 2.00018790482477e-13f);
    p = __fmaf_rn(x2, p, -8.60467152213735e-11f);
    p = __fmaf_rn(x2, p,  5.12229709037114e-08f);
    p = __fmaf_rn(x2, p,  1.48572235717979e-05f);
    p = __fmaf_rn(x2, p,  6.37261928875436e-04f);
    p = __fmaf_rn(x2, p,  4.89352455891786e-03f);
    float num = __fmul_rn(xc, p);
    float q = __fmaf_rn(x2, 1.19825839466702e-06f, 1.18534705686654e-04f);
    q = __fmaf_rn(x2, q, 2.26843463243900e-03f);
    q = __fmaf_rn(x2, q, 4.89352518554385e-03f);
    float r = __fdiv_rn(num, q);
    float ft = (ax < 0.0004f) ? x : r;
    return (ax < 20.0f) ? ft : copysignf(1.0f, x);
}
__device__ __forceinline__ float sigmoid_xla(float x) {
    float t = tanh_xla(__fmul_rn(0.5f, x));
    return __fadd_rn(__fmul_rn(0.5f, t), 0.5f);
}

// ---------------- dummy launch-shifter (for ncu capture alignment) ----------
__global__ void kdummy() { if (threadIdx.x == 0) g_dummy = 1; }

// =====================================================================
// K1: g_table[v][ng] = embed[v] . W_ih[dir][g]  (round-9 version)
// =====================================================================
#define K1_AS_BYTES (16 * 130 * 8)          // float2[16][130]
#define K1_BS_BYTES (16 * 132 * 4)          // float [16][132]
#define K1_SMEM     (2 * K1_AS_BYTES + 2 * K1_BS_BYTES)

__global__ void __launch_bounds__(256, 2) k1_table(
    const float* __restrict__ embed,
    const float* __restrict__ w_ih_f, const float* __restrict__ w_ih_r)
{
    extern __shared__ __align__(16) char k1sm[];
    float2* AsBuf[2] = { (float2*)k1sm, (float2*)(k1sm + K1_AS_BYTES) };
    float*  BsBuf[2] = { (float*)(k1sm + 2 * K1_AS_BYTES),
                         (float*)(k1sm + 2 * K1_AS_BYTES + K1_BS_BYTES) };

    const int tid  = threadIdx.x;
    const int row0 = blockIdx.y * 128;
    const int n0   = blockIdx.x * 128;
    const int tx = tid & 15, ty = tid >> 4;

    ull acc[8][4];
    #pragma unroll
    for (int m = 0; m < 8; ++m)
        #pragma unroll
        for (int n2 = 0; n2 < 4; ++n2) acc[m][n2] = 0ull;

    float ra[8], rb[8];

    auto ldg_tile = [&](int t) {
        const int k0 = t * 16;
        #pragma unroll
        for (int i = 0; i < 8; ++i) {
            int lin = tid + 256 * i;
            int m = lin >> 4, k = lin & 15;
            ra[i] = embed[(size_t)(row0 + m) * EDIM + k0 + k];
            int ng = n0 + m;
            const float* src = (ng >= 512) ? w_ih_r : w_ih_f;
            rb[i] = src[(size_t)(ng & 511) * EDIM + k0 + k];
        }
    };
    auto sts_tile = [&](int buf) {
        #pragma unroll
        for (int i = 0; i < 8; ++i) {
            int lin = tid + 256 * i;
            int m = lin >> 4, k = lin & 15;
            AsBuf[buf][k * 130 + m] = make_float2(ra[i], ra[i]);
            BsBuf[buf][k * 132 + m] = rb[i];
        }
    };

    ldg_tile(0);
    sts_tile(0);
    __syncthreads();

    for (int t = 0; t < 16; ++t) {
        const int buf = t & 1;
        if (t < 15) ldg_tile(t + 1);

        const float2* As = AsBuf[buf];
        const float*  Bs = BsBuf[buf];
        #pragma unroll
        for (int kk = 0; kk < 16; ++kk) {
            ulonglong2 a01 = *(const ulonglong2*)&As[kk * 130 + ty * 8];
            ulonglong2 a23 = *(const ulonglong2*)&As[kk * 130 + ty * 8 + 2];
            ulonglong2 a45 = *(const ulonglong2*)&As[kk * 130 + ty * 8 + 4];
            ulonglong2 a67 = *(const ulonglong2*)&As[kk * 130 + ty * 8 + 6];
            ulonglong2 b01 = *(const ulonglong2*)&Bs[kk * 132 + tx * 8];
            ulonglong2 b23 = *(const ulonglong2*)&Bs[kk * 132 + tx * 8 + 4];
            ull ad[8] = { a01.x, a01.y, a23.x, a23.y, a45.x, a45.y, a67.x, a67.y };
            ull bp[4] = { b01.x, b01.y, b23.x, b23.y };
            #pragma unroll
            for (int m = 0; m < 8; ++m)
                #pragma unroll
                for (int n2 = 0; n2 < 4; ++n2)
                    fma2(acc[m][n2], ad[m], bp[n2]);
        }

        if (t < 15) {
            sts_tile(buf ^ 1);
            __syncthreads();
        }
    }

    #pragma unroll
    for (int m = 0; m < 8; ++m) {
        int row = row0 + ty * 8 + m;
        float o[8];
        #pragma unroll
        for (int n2 = 0; n2 < 4; ++n2)
            unpack2(acc[m][n2], o[2 * n2], o[2 * n2 + 1]);
        float* dst = g_table + (size_t)row * 1024 + n0 + tx * 8;
        *(float4*)dst       = make_float4(o[0], o[1], o[2], o[3]);
        *(float4*)(dst + 4) = make_float4(o[4], o[5], o[6], o[7]);
    }
}

// =====================================================================
// K2: LSTM recurrence — TWO same-direction chains per CTA (shared W_hh).
// 64 CTAs x 256 threads. Thread t: u = t>>1, par = t&1, rA = par*128+u;
// rows (rA, rA+256) packed in f32x2. Weights: k=0..103 in regs (104 ull),
// k=104..127 in smem (12 ulonglong2 groups). Matvecs A then B reuse the
// same accumulators; tails interleaved (ILP); one barrier/step.
// Per-chain math identical to round 11 -> bit-identical h.
// =====================================================================
#define K2_WSQ  12
#define K2_WS   (K2_WSQ * 256 * 16)            // 49152 B
#define K2_SMEM (K2_WS + 4096 + 8192)          // + 4 h-buffers + 2 tok arrays

__device__ __forceinline__ void k2_matvec(
    const ulonglong2* __restrict__ hp, const ull* __restrict__ wregP,
    const ulonglong2* __restrict__ wsP2, int t,
    float &hwLo, float &hwHi)
{
    ull acc0 = 0ull, acc1 = 0ull, acc2 = 0ull, acc3 = 0ull;
    #pragma unroll
    for (int q = 0; q < 16; ++q) {              // k = 0..31 (regs)
        ulonglong2 h2 = hp[q];
        fma2(acc0, h2.x, wregP[2 * q]);
        fma2(acc0, h2.y, wregP[2 * q + 1]);
    }
    #pragma unroll
    for (int q = 16; q < 32; ++q) {             // k = 32..63 (regs)
        ulonglong2 h2 = hp[q];
        fma2(acc1, h2.x, wregP[2 * q]);
        fma2(acc1, h2.y, wregP[2 * q + 1]);
    }
    #pragma unroll
    for (int q = 32; q < 48; ++q) {             // k = 64..95 (regs)
        ulonglong2 h2 = hp[q];
        fma2(acc2, h2.x, wregP[2 * q]);
        fma2(acc2, h2.y, wregP[2 * q + 1]);
    }
    #pragma unroll
    for (int q = 48; q < 52; ++q) {             // k = 96..103 (regs)
        ulonglong2 h2 = hp[q];
        fma2(acc3, h2.x, wregP[2 * q]);
        fma2(acc3, h2.y, wregP[2 * q + 1]);
    }
    #pragma unroll
    for (int qq = 0; qq < K2_WSQ; ++qq) {       // k = 104..127 (smem)
        ulonglong2 h2 = hp[52 + qq];
        ulonglong2 w2 = wsP2[qq * 256 + t];
        fma2(acc3, h2.x, w2.x);
        fma2(acc3, h2.y, w2.y);
    }
    float a0l, a0h, a1l, a1h, a2l, a2h, a3l, a3h;
    unpack2(acc0, a0l, a0h);
    unpack2(acc1, a1l, a1h);
    unpack2(acc2, a2l, a2h);
    unpack2(acc3, a3l, a3h);
    hwLo = __fadd_rn(__fadd_rn(a0l, a1l), __fadd_rn(a2l, a3l));
    hwHi = __fadd_rn(__fadd_rn(a0h, a1h), __fadd_rn(a2h, a3h));
}

__global__ void __launch_bounds__(256, 1) k2_lstm(
    const int* __restrict__ sentences,
    const float* __restrict__ w_hh_f, const float* __restrict__ w_hh_r,
    const float* __restrict__ b_ih_f, const float* __restrict__ b_hh_f,
    const float* __restrict__ b_ih_r, const float* __restrict__ b_hh_r)
{
    extern __shared__ __align__(16) char sm[];
    ulonglong2* wsP2 = (ulonglong2*)sm;                  // [12][256] k=104..127
    float2* hdA0 = (float2*)(sm + K2_WS);                // [128] chain A {h,h}
    float2* hdA1 = (float2*)(sm + K2_WS + 1024);
    float2* hdB0 = (float2*)(sm + K2_WS + 2048);         // [128] chain B
    float2* hdB1 = (float2*)(sm + K2_WS + 3072);
    int* toksA = (int*)(sm + K2_WS + 4096);              // [1024]
    int* toksB = (int*)(sm + K2_WS + 4096 + 4096);       // [1024]

    const int t   = threadIdx.x;
    const int u   = t >> 1;
    const int par = t & 1;
    const int rA  = par * 128 + u;
    const int dir = blockIdx.x & 1;
    const int bp  = blockIdx.x >> 1;
    const int bA  = bp * 2;
    const int bB  = bp * 2 + 1;
    const float* Whh = dir ? w_hh_r : w_hh_f;
    const float* bi  = dir ? b_ih_r : b_ih_f;
    const float* bh  = dir ? b_hh_r : b_hh_f;

    const float biasA = __fadd_rn(bi[rA],       bh[rA]);
    const float biasB = __fadd_rn(bi[rA + 256], bh[rA + 256]);

    #pragma unroll
    for (int it = 0; it < 4; ++it) {
        int i = t + 256 * it;
        int tkA = sentences[bA * SS + i];
        int tkB = sentences[bB * SS + i];
        if (tkA < 0) tkA = 0;  if (tkA >= V) tkA = V - 1;
        if (tkB < 0) tkB = 0;  if (tkB >= V) tkB = V - 1;
        toksA[i] = tkA;
        toksB[i] = tkB;
    }

    ull wregP[104];                 // k = 0..103, {w_rA[k], w_rA+256[k]}
    {
        const float* r0 = Whh + (size_t)rA * HDIM;
        const float* r1 = Whh + (size_t)(rA + 256) * HDIM;
        #pragma unroll
        for (int k = 0; k < 104; ++k) wregP[k] = pack2(r0[k], r1[k]);
        #pragma unroll
        for (int qq = 0; qq < K2_WSQ; ++qq) {
            int k = 104 + 2 * qq;
            ulonglong2 w2;
            w2.x = pack2(r0[k],     r1[k]);
            w2.y = pack2(r0[k + 1], r1[k + 1]);
            wsP2[qq * 256 + t] = w2;
        }
    }

    float cstA = 0.0f, cstB = 0.0f;     // live on even threads
    if (par == 0) {
        hdA0[u] = make_float2(0.0f, 0.0f);
        hdB0[u] = make_float2(0.0f, 0.0f);
    }
    __syncthreads();

    const float* tb = g_table + dir * 512 + rA;
    int pos = dir ? (SS - 1) : 0;
    const int stp = dir ? -1 : 1;

    float zlA = tb[(size_t)toksA[pos] * 1024];
    float zhA = tb[(size_t)toksA[pos] * 1024 + 256];
    float zlB = tb[(size_t)toksB[pos] * 1024];
    float zhB = tb[(size_t)toksB[pos] * 1024 + 256];

    for (int s = 0; s < SS; ++s) {
        // prefetch next step's projections for both chains
        float nzlA = 0.f, nzhA = 0.f, nzlB = 0.f, nzhB = 0.f;
        if (s + 1 < SS) {
            const float* npA = tb + (size_t)toksA[pos + stp] * 1024;
            const float* npB = tb + (size_t)toksB[pos + stp] * 1024;
            nzlA = npA[0]; nzhA = npA[256];
            nzlB = npB[0]; nzhB = npB[256];
        }

        const ulonglong2* hpA =
            (s & 1) ? (const ulonglong2*)hdA1 : (const ulonglong2*)hdA0;
        const ulonglong2* hpB =
            (s & 1) ? (const ulonglong2*)hdB1 : (const ulonglong2*)hdB0;

        float hwAlo, hwAhi, hwBlo, hwBhi;
        k2_matvec(hpA, wregP, wsP2, t, hwAlo, hwAhi);
        k2_matvec(hpB, wregP, wsP2, t, hwBlo, hwBhi);

        float zA0 = __fadd_rn(__fadd_rn(zlA, hwAlo), biasA);
        float zA1 = __fadd_rn(__fadd_rn(zhA, hwAhi), biasB);
        float zB0 = __fadd_rn(__fadd_rn(zlB, hwBlo), biasA);
        float zB1 = __fadd_rn(__fadd_rn(zhB, hwBhi), biasB);

        ull opkA = __shfl_xor_sync(0xffffffffu, pack2(zA0, zA1), 1);
        ull opkB = __shfl_xor_sync(0xffffffffu, pack2(zB0, zB1), 1);

        if (par == 0) {
            // chain A: own (i,g), partner (f,o)
            float zfA, zoA; unpack2(opkA, zfA, zoA);
            float zfB, zoB; unpack2(opkB, zfB, zoB);
            float ivA = sigmoid_xla(zA0);
            float fvA = sigmoid_xla(zfA);
            float gvA = tanh_xla(zA1);
            float ovA = sigmoid_xla(zoA);
            float ivB = sigmoid_xla(zB0);
            float fvB = sigmoid_xla(zfB);
            float gvB = tanh_xla(zB1);
            float ovB = sigmoid_xla(zoB);
            cstA = __fadd_rn(__fmul_rn(fvA, cstA), __fmul_rn(ivA, gvA));
            cstB = __fadd_rn(__fmul_rn(fvB, cstB), __fmul_rn(ivB, gvB));
            float hvA = __fmul_rn(ovA, tanh_xla(cstA));
            float hvB = __fmul_rn(ovB, tanh_xla(cstB));
            float2* hdAN = (s & 1) ? hdA0 : hdA1;
            float2* hdBN = (s & 1) ? hdB0 : hdB1;
            hdAN[u] = make_float2(hvA, hvA);
            hdBN[u] = make_float2(hvB, hvB);
            g_h[(size_t)(pos * BB + bA) * 256 + dir * 128 + u] = hvA;
            g_h[(size_t)(pos * BB + bB) * 256 + dir * 128 + u] = hvB;
        }
        __syncthreads();

        zlA = nzlA; zhA = nzhA; zlB = nzlB; zhB = nzhB;
        pos += stp;
    }
}

// =====================================================================
// K3: emissions. One warp per (s,b).
// =====================================================================
__global__ void __launch_bounds__(256) k3_emis(
    const float* __restrict__ w_out, const float* __restrict__ b_out)
{
    __shared__ float wsm[4 * 256];
    int tid = threadIdx.x;
    #pragma unroll
    for (int it = 0; it < 4; ++it) wsm[tid + 256 * it] = w_out[tid + 256 * it];
    __syncthreads();

    int w = tid >> 5, lane = tid & 31;
    int gid = blockIdx.x * 8 + w;
    int b = gid & 63, s = gid >> 6;
    const float* hrow = g_h + (size_t)(s * BB + b) * 256;

    float a0 = 0.f, a1 = 0.f, a2 = 0.f, a3 = 0.f;
    #pragma unroll
    for (int it = 0; it < 8; ++it) {
        int jj = it * 32 + lane;
        float hv = hrow[jj];
        a0 = __fmaf_rn(hv, wsm[jj],       a0);
        a1 = __fmaf_rn(hv, wsm[256 + jj], a1);
        a2 = __fmaf_rn(hv, wsm[512 + jj], a2);
        a3 = __fmaf_rn(hv, wsm[768 + jj], a3);
    }
    #pragma unroll
    for (int off = 16; off; off >>= 1) {
        a0 = __fadd_rn(a0, __shfl_xor_sync(0xffffffffu, a0, off));
        a1 = __fadd_rn(a1, __shfl_xor_sync(0xffffffffu, a1, off));
        a2 = __fadd_rn(a2, __shfl_xor_sync(0xffffffffu, a2, off));
        a3 = __fadd_rn(a3, __shfl_xor_sync(0xffffffffu, a3, off));
    }
    if (lane == 0) {
        float* dst = g_feats + (size_t)(b * SS + s) * 4;
        dst[0] = __fadd_rn(a0, b_out[0]);
        dst[1] = __fadd_rn(a1, b_out[1]);
        dst[2] = __fadd_rn(a2, b_out[2]);
        dst[3] = __fadd_rn(a3, b_out[3]);
    }
}

// =====================================================================
// K4: Viterbi (float output) — unchanged; clock canary.
// =====================================================================
__global__ void __launch_bounds__(128) k4_viterbi(
    const float* __restrict__ start_t, const float* __restrict__ end_t,
    const float* __restrict__ trans, float* __restrict__ out)
{
    __shared__ float fs[SS * 4];
    __shared__ unsigned char bp[SS * 4];
    __shared__ int path[SS];
    int tid = threadIdx.x;
    int b = blockIdx.x;

    const float* src = g_feats + (size_t)b * SS * 4;
    for (int i = tid; i < SS * 4; i += 128) fs[i] = src[i];
    __syncthreads();

    if (tid < 4) {
        const int t = tid;
        float tr0 = trans[0 * 4 + t], tr1 = trans[1 * 4 + t];
        float tr2 = trans[2 * 4 + t], tr3 = trans[3 * 4 + t];
        float score = __fadd_rn(start_t[t], fs[t]);
        for (int s = 1; s < SS; ++s) {
            float s0 = __shfl_sync(0xFu, score, 0);
            float s1 = __shfl_sync(0xFu, score, 1);
            float s2 = __shfl_sync(0xFu, score, 2);
            float s3 = __shfl_sync(0xFu, score, 3);
            float e  = fs[s * 4 + t];
            float v0 = __fadd_rn(__fadd_rn(s0, tr0), e);
            float v1 = __fadd_rn(__fadd_rn(s1, tr1), e);
            float v2 = __fadd_rn(__fadd_rn(s2, tr2), e);
            float v3 = __fadd_rn(__fadd_rn(s3, tr3), e);
            float best = v0; int bpi = 0;
            if (v1 > best) { best = v1; bpi = 1; }
            if (v2 > best) { best = v2; bpi = 2; }
            if (v3 > best) { best = v3; bpi = 3; }
            score = best;
            bp[s * 4 + t] = (unsigned char)bpi;
        }
        score = __fadd_rn(score, end_t[t]);
        float f0 = __shfl_sync(0xFu, score, 0);
        float f1 = __shfl_sync(0xFu, score, 1);
        float f2 = __shfl_sync(0xFu, score, 2);
        float f3 = __shfl_sync(0xFu, score, 3);
        __syncwarp(0xFu);
        if (t == 0) {
            float best = f0; int last = 0;
            if (f1 > best) { best = f1; last = 1; }
            if (f2 > best) { best = f2; last = 2; }
            if (f3 > best) { best = f3; last = 3; }
            int tag = last;
            path[SS - 1] = tag;
            for (int s = SS - 1; s >= 1; --s) {
                tag = bp[s * 4 + tag];
                path[s - 1] = tag;
            }
        }
    }
    __syncthreads();
    for (int i = tid; i < SS; i += 128)
        out[b * SS + i] = (float)path[i];
}

// =====================================================================
extern "C" void kernel_launch(void* const* d_in, const int* in_sizes, int n_in,
                              void* d_out, int out_size)
{
    const int*   sentences = (const int*)d_in[0];
    const float* embed   = (const float*)d_in[1];
    const float* w_ih_f  = (const float*)d_in[2];
    const float* w_hh_f  = (const float*)d_in[3];
    const float* b_ih_f  = (const float*)d_in[4];
    const float* b_hh_f  = (const float*)d_in[5];
    const float* w_ih_r  = (const float*)d_in[6];
    const float* w_hh_r  = (const float*)d_in[7];
    const float* b_ih_r  = (const float*)d_in[8];
    const float* b_hh_r  = (const float*)d_in[9];
    const float* w_out   = (const float*)d_in[10];
    const float* b_out   = (const float*)d_in[11];
    const float* start_t = (const float*)d_in[12];
    const float* end_t   = (const float*)d_in[13];
    const float* trans   = (const float*)d_in[14];

    // launch-shifters keep ncu's capture window on k2_lstm
    kdummy<<<1, 32>>>();
    kdummy<<<1, 32>>>();

    cudaFuncSetAttribute(k1_table, cudaFuncAttributeMaxDynamicSharedMemorySize, K1_SMEM);
    dim3 g1(8, 250);
    k1_table<<<g1, 256, K1_SMEM>>>(embed, w_ih_f, w_ih_r);

    cudaFuncSetAttribute(k2_lstm, cudaFuncAttributeMaxDynamicSharedMemorySize, K2_SMEM);
    k2_lstm<<<64, 256, K2_SMEM>>>(sentences, w_hh_f, w_hh_r,
                                  b_ih_f, b_hh_f, b_ih_r, b_hh_r);

    k3_emis<<<8192, 256>>>(w_out, b_out);
    k4_viterbi<<<64, 128>>>(start_t, end_t, trans, (float*)d_out);
}

// round 15
// speedup vs baseline: 2.0851x; 2.0851x over previous
#include <cuda_runtime.h>
#include <math.h>

#define V 32000
#define EDIM 256
#define HDIM 128
#define BB 64
#define SS 1024
#define TT 4

typedef unsigned long long ull;

// ---------------- scratch (static device globals) ---------------------------
__device__ float g_table[V * 1024];     // [v][dir*512 + g] : PURE x@W_ih.T
__device__ float g_h[SS * BB * 256];    // [s][b][dir*128 + j]
__device__ float g_feats[BB * SS * TT]; // [b][s][t]
__device__ int   g_dummy;

// ---------------- packed f32x2 helpers --------------------------------------
__device__ __forceinline__ void fma2(ull &acc, ull a, ull b) {
    asm("fma.rn.f32x2 %0, %1, %2, %0;" : "+l"(acc) : "l"(a), "l"(b));
}
__device__ __forceinline__ ull pack2(float lo, float hi) {
    ull r; asm("mov.b64 %0, {%1, %2};" : "=l"(r) : "f"(lo), "f"(hi)); return r;
}
__device__ __forceinline__ void unpack2(ull v, float &lo, float &hi) {
    asm("mov.b64 {%0, %1}, %2;" : "=f"(lo), "=f"(hi) : "l"(v));
}

// ---------------- XLA-GPU exact nonlinearities ------------------------------
__device__ __forceinline__ float tanh_xla(float x) {
    float ax = fabsf(x);
    float xc = fminf(fmaxf(x, -7.90531110763549805f), 7.90531110763549805f);
    float x2 = __fmul_rn(xc, xc);
    float p = __fmaf_rn(x2, -2.76076847742355e-16f, 2.00018790482477e-13f);
    p = __fmaf_rn(x2, p, -8.60467152213735e-11f);
    p = __fmaf_rn(x2, p,  5.12229709037114e-08f);
    p = __fmaf_rn(x2, p,  1.48572235717979e-05f);
    p = __fmaf_rn(x2, p,  6.37261928875436e-04f);
    p = __fmaf_rn(x2, p,  4.89352455891786e-03f);
    float num = __fmul_rn(xc, p);
    float q = __fmaf_rn(x2, 1.19825839466702e-06f, 1.18534705686654e-04f);
    q = __fmaf_rn(x2, q, 2.26843463243900e-03f);
    q = __fmaf_rn(x2, q, 4.89352518554385e-03f);
    float r = __fdiv_rn(num, q);
    float ft = (ax < 0.0004f) ? x : r;
    return (ax < 20.0f) ? ft : copysignf(1.0f, x);
}
__device__ __forceinline__ float sigmoid_xla(float x) {
    float t = tanh_xla(__fmul_rn(0.5f, x));
    return __fadd_rn(__fmul_rn(0.5f, t), 0.5f);
}

// ---------------- dummy launch-shifter (for ncu capture alignment) ----------
__global__ void kdummy() { if (threadIdx.x == 0) g_dummy = 1; }

// =====================================================================
// K1: g_table[v][ng] = embed[v] . W_ih[dir][g]  (pure projection)
// ROUND-10 CROSSBAR FIX, retested under good clock: As stored naturally
// (no {a,a} smem duplication); duplicated multiplicand built with register
// mov.b64 packs. 64B smem per 64 MAC per thread -> fma-bound.
// fma2 chain order unchanged -> bit-identical table (verified r10).
// =====================================================================
#define K1_TILE_BYTES (16 * 132 * 4)        // float[16][132]
#define K1_SMEM       (4 * K1_TILE_BYTES)   // As x2 bufs + Bs x2 bufs

__global__ void __launch_bounds__(256, 2) k1_table(
    const float* __restrict__ embed,
    const float* __restrict__ w_ih_f, const float* __restrict__ w_ih_r)
{
    extern __shared__ __align__(16) char k1sm[];
    float* AsBuf[2] = { (float*)k1sm, (float*)(k1sm + K1_TILE_BYTES) };
    float* BsBuf[2] = { (float*)(k1sm + 2 * K1_TILE_BYTES),
                        (float*)(k1sm + 3 * K1_TILE_BYTES) };

    const int tid  = threadIdx.x;
    const int row0 = blockIdx.y * 128;
    const int n0   = blockIdx.x * 128;
    const int tx = tid & 15, ty = tid >> 4;

    ull acc[8][4];
    #pragma unroll
    for (int m = 0; m < 8; ++m)
        #pragma unroll
        for (int n2 = 0; n2 < 4; ++n2) acc[m][n2] = 0ull;

    float ra[8], rb[8];

    auto ldg_tile = [&](int t) {
        const int k0 = t * 16;
        #pragma unroll
        for (int i = 0; i < 8; ++i) {
            int lin = tid + 256 * i;
            int m = lin >> 4, k = lin & 15;
            ra[i] = embed[(size_t)(row0 + m) * EDIM + k0 + k];
            int ng = n0 + m;
            const float* src = (ng >= 512) ? w_ih_r : w_ih_f;
            rb[i] = src[(size_t)(ng & 511) * EDIM + k0 + k];
        }
    };
    auto sts_tile = [&](int buf) {
        #pragma unroll
        for (int i = 0; i < 8; ++i) {
            int lin = tid + 256 * i;
            int m = lin >> 4, k = lin & 15;
            AsBuf[buf][k * 132 + m] = ra[i];
            BsBuf[buf][k * 132 + m] = rb[i];
        }
    };

    ldg_tile(0);
    sts_tile(0);
    __syncthreads();

    for (int t = 0; t < 16; ++t) {
        const int buf = t & 1;
        if (t < 15) ldg_tile(t + 1);

        const float* As = AsBuf[buf];
        const float* Bs = BsBuf[buf];
        #pragma unroll
        for (int kk = 0; kk < 16; ++kk) {
            float4 a0 = *(const float4*)&As[kk * 132 + ty * 8];
            float4 a1 = *(const float4*)&As[kk * 132 + ty * 8 + 4];
            ulonglong2 b01 = *(const ulonglong2*)&Bs[kk * 132 + tx * 8];
            ulonglong2 b23 = *(const ulonglong2*)&Bs[kk * 132 + tx * 8 + 4];
            float am[8] = { a0.x, a0.y, a0.z, a0.w, a1.x, a1.y, a1.z, a1.w };
            ull bp[4] = { b01.x, b01.y, b23.x, b23.y };
            #pragma unroll
            for (int m = 0; m < 8; ++m) {
                ull ad = pack2(am[m], am[m]);
                #pragma unroll
                for (int n2 = 0; n2 < 4; ++n2)
                    fma2(acc[m][n2], ad, bp[n2]);
            }
        }

        if (t < 15) {
            sts_tile(buf ^ 1);
            __syncthreads();
        }
    }

    #pragma unroll
    for (int m = 0; m < 8; ++m) {
        int row = row0 + ty * 8 + m;
        float o[8];
        #pragma unroll
        for (int n2 = 0; n2 < 4; ++n2)
            unpack2(acc[m][n2], o[2 * n2], o[2 * n2 + 1]);
        float* dst = g_table + (size_t)row * 1024 + n0 + tx * 8;
        *(float4*)dst       = make_float4(o[0], o[1], o[2], o[3]);
        *(float4*)(dst + 4) = make_float4(o[4], o[5], o[6], o[7]);
    }
}

// =====================================================================
// K2: LSTM recurrence, f32x2. 128 CTAs = (b, dir), 256 threads.
// Round-12 base (112 reg-pairs + 8 smem groups, single barrier) plus
// PARALLEL NONLINEARITY TAIL: even thread computes sigmoid(zi), tanh(zg);
// odd computes sigmoid(zf), sigmoid(zo) via one tanh eval each; one shfl
// exchanges the VALUES. Bit-identical gate values -> bit-identical h.
// =====================================================================
#define K2_WSQ  8
#define K2_WS   (K2_WSQ * 256 * 16)            // ulonglong2[8][256] = 32 KB
#define K2_SMEM (K2_WS + 2048 + 4096)          // + hd[2][128] float2 + toks

__global__ void __launch_bounds__(256, 1) k2_lstm(
    const int* __restrict__ sentences,
    const float* __restrict__ w_hh_f, const float* __restrict__ w_hh_r,
    const float* __restrict__ b_ih_f, const float* __restrict__ b_hh_f,
    const float* __restrict__ b_ih_r, const float* __restrict__ b_hh_r)
{
    extern __shared__ __align__(16) char sm[];
    ulonglong2* wsP2 = (ulonglong2*)sm;                 // [8][256] : k=112..127
    float2* hd0  = (float2*)(sm + K2_WS);               // [128] {h,h}
    float2* hd1  = (float2*)(sm + K2_WS + 1024);        // [128] {h,h}
    int*    toks = (int*)  (sm + K2_WS + 2048);         // [1024]

    const int t   = threadIdx.x;
    const int u   = t >> 1;          // hidden unit 0..127
    const int par = t & 1;           // 0: rows (i_u, g_u)  1: rows (f_u, o_u)
    const int rA  = par * 128 + u;
    const int dir = blockIdx.x & 1;
    const int b   = blockIdx.x >> 1;
    const float* Whh = dir ? w_hh_r : w_hh_f;
    const float* bi  = dir ? b_ih_r : b_ih_f;
    const float* bh  = dir ? b_hh_r : b_hh_f;

    const float bA = __fadd_rn(bi[rA],       bh[rA]);
    const float bB = __fadd_rn(bi[rA + 256], bh[rA + 256]);

    #pragma unroll
    for (int it = 0; it < 4; ++it) {
        int tk = sentences[b * SS + t + 256 * it];
        if (tk < 0) tk = 0;
        if (tk >= V) tk = V - 1;
        toks[t + 256 * it] = tk;
    }

    ull wregP[112];                // k = 0..111, {w_rA[k], w_rA+256[k]}
    {
        const float* r0 = Whh + (size_t)rA * HDIM;
        const float* r1 = Whh + (size_t)(rA + 256) * HDIM;
        #pragma unroll
        for (int k = 0; k < 112; ++k) wregP[k] = pack2(r0[k], r1[k]);
        #pragma unroll
        for (int qq = 0; qq < K2_WSQ; ++qq) {
            int k = 112 + 2 * qq;
            ulonglong2 w2;
            w2.x = pack2(r0[k],     r1[k]);
            w2.y = pack2(r0[k + 1], r1[k + 1]);
            wsP2[qq * 256 + t] = w2;
        }
    }

    float cst = 0.0f;
    if (par == 0) hd0[u] = make_float2(0.0f, 0.0f);
    __syncthreads();

    const float* tb = g_table + dir * 512 + rA;
    int pos = dir ? (SS - 1) : 0;
    const int stp = dir ? -1 : 1;

    const float* zrow = tb + (size_t)toks[pos] * 1024;
    float zl = zrow[0];
    float zh = zrow[256];

    for (int s = 0; s < SS; ++s) {
        float nzl = 0.0f, nzh = 0.0f;
        if (s + 1 < SS) {
            const float* np = tb + (size_t)toks[pos + stp] * 1024;
            nzl = np[0]; nzh = np[256];
        }

        const ulonglong2* hp =
            (s & 1) ? (const ulonglong2*)hd1 : (const ulonglong2*)hd0;

        ull acc0 = 0ull, acc1 = 0ull, acc2 = 0ull, acc3 = 0ull;
        #pragma unroll
        for (int q = 0; q < 16; ++q) {              // k = 0..31 (regs)
            ulonglong2 h2 = hp[q];
            fma2(acc0, h2.x, wregP[2 * q]);
            fma2(acc0, h2.y, wregP[2 * q + 1]);
        }
        #pragma unroll
        for (int q = 16; q < 32; ++q) {             // k = 32..63 (regs)
            ulonglong2 h2 = hp[q];
            fma2(acc1, h2.x, wregP[2 * q]);
            fma2(acc1, h2.y, wregP[2 * q + 1]);
        }
        #pragma unroll
        for (int q = 32; q < 48; ++q) {             // k = 64..95 (regs)
            ulonglong2 h2 = hp[q];
            fma2(acc2, h2.x, wregP[2 * q]);
            fma2(acc2, h2.y, wregP[2 * q + 1]);
        }
        #pragma unroll
        for (int q = 48; q < 56; ++q) {             // k = 96..111 (regs)
            ulonglong2 h2 = hp[q];
            fma2(acc3, h2.x, wregP[2 * q]);
            fma2(acc3, h2.y, wregP[2 * q + 1]);
        }
        #pragma unroll
        for (int qq = 0; qq < K2_WSQ; ++qq) {       // k = 112..127 (smem)
            ulonglong2 h2 = hp[56 + qq];
            ulonglong2 w2 = wsP2[qq * 256 + t];
            fma2(acc3, h2.x, w2.x);
            fma2(acc3, h2.y, w2.y);
        }

        float a0l, a0h, a1l, a1h, a2l, a2h, a3l, a3h;
        unpack2(acc0, a0l, a0h);
        unpack2(acc1, a1l, a1h);
        unpack2(acc2, a2l, a2h);
        unpack2(acc3, a3l, a3h);
        float hwA = __fadd_rn(__fadd_rn(a0l, a1l), __fadd_rn(a2l, a3l));
        float hwB = __fadd_rn(__fadd_rn(a0h, a1h), __fadd_rn(a2h, a3h));

        float zA = __fadd_rn(__fadd_rn(zl, hwA), bA);   // par0: zi, par1: zf
        float zB = __fadd_rn(__fadd_rn(zh, hwB), bB);   // par0: zg, par1: zo

        // parallel nonlinearity tail:
        //   vA = sigmoid(zA) on both threads (i or f)
        //   vB = par0 ? tanh(zB) : sigmoid(zB)  (g or o) via ONE tanh eval
        float vA = sigmoid_xla(zA);
        float targ = par ? __fmul_rn(0.5f, zB) : zB;
        float tv   = tanh_xla(targ);
        float vB   = par ? __fadd_rn(__fmul_rn(0.5f, tv), 0.5f) : tv;

        ull opk = __shfl_xor_sync(0xffffffffu, pack2(vA, vB), 1);

        if (par == 0) {
            float iv = vA, gv = vB;
            float fv, ov; unpack2(opk, fv, ov);
            cst = __fadd_rn(__fmul_rn(fv, cst), __fmul_rn(iv, gv));
            float hv = __fmul_rn(ov, tanh_xla(cst));
            float2* hdN = (s & 1) ? hd0 : hd1;
            hdN[u] = make_float2(hv, hv);
            g_h[(size_t)(pos * BB + b) * 256 + dir * 128 + u] = hv;
        }
        __syncthreads();

        zl = nzl; zh = nzh;
        pos += stp;
    }
}

// =====================================================================
// K3: emissions. One warp per (s,b).
// =====================================================================
__global__ void __launch_bounds__(256) k3_emis(
    const float* __restrict__ w_out, const float* __restrict__ b_out)
{
    __shared__ float wsm[4 * 256];
    int tid = threadIdx.x;
    #pragma unroll
    for (int it = 0; it < 4; ++it) wsm[tid + 256 * it] = w_out[tid + 256 * it];
    __syncthreads();

    int w = tid >> 5, lane = tid & 31;
    int gid = blockIdx.x * 8 + w;
    int b = gid & 63, s = gid >> 6;
    const float* hrow = g_h + (size_t)(s * BB + b) * 256;

    float a0 = 0.f, a1 = 0.f, a2 = 0.f, a3 = 0.f;
    #pragma unroll
    for (int it = 0; it < 8; ++it) {
        int jj = it * 32 + lane;
        float hv = hrow[jj];
        a0 = __fmaf_rn(hv, wsm[jj],       a0);
        a1 = __fmaf_rn(hv, wsm[256 + jj], a1);
        a2 = __fmaf_rn(hv, wsm[512 + jj], a2);
        a3 = __fmaf_rn(hv, wsm[768 + jj], a3);
    }
    #pragma unroll
    for (int off = 16; off; off >>= 1) {
        a0 = __fadd_rn(a0, __shfl_xor_sync(0xffffffffu, a0, off));
        a1 = __fadd_rn(a1, __shfl_xor_sync(0xffffffffu, a1, off));
        a2 = __fadd_rn(a2, __shfl_xor_sync(0xffffffffu, a2, off));
        a3 = __fadd_rn(a3, __shfl_xor_sync(0xffffffffu, a3, off));
    }
    if (lane == 0) {
        float* dst = g_feats + (size_t)(b * SS + s) * 4;
        dst[0] = __fadd_rn(a0, b_out[0]);
        dst[1] = __fadd_rn(a1, b_out[1]);
        dst[2] = __fadd_rn(a2, b_out[2]);
        dst[3] = __fadd_rn(a3, b_out[3]);
    }
}

// =====================================================================
// K4: Viterbi (float output) — unchanged; clock canary.
// =====================================================================
__global__ void __launch_bounds__(128) k4_viterbi(
    const float* __restrict__ start_t, const float* __restrict__ end_t,
    const float* __restrict__ trans, float* __restrict__ out)
{
    __shared__ float fs[SS * 4];
    __shared__ unsigned char bp[SS * 4];
    __shared__ int path[SS];
    int tid = threadIdx.x;
    int b = blockIdx.x;

    const float* src = g_feats + (size_t)b * SS * 4;
    for (int i = tid; i < SS * 4; i += 128) fs[i] = src[i];
    __syncthreads();

    if (tid < 4) {
        const int t = tid;
        float tr0 = trans[0 * 4 + t], tr1 = trans[1 * 4 + t];
        float tr2 = trans[2 * 4 + t], tr3 = trans[3 * 4 + t];
        float score = __fadd_rn(start_t[t], fs[t]);
        for (int s = 1; s < SS; ++s) {
            float s0 = __shfl_sync(0xFu, score, 0);
            float s1 = __shfl_sync(0xFu, score, 1);
            float s2 = __shfl_sync(0xFu, score, 2);
            float s3 = __shfl_sync(0xFu, score, 3);
            float e  = fs[s * 4 + t];
            float v0 = __fadd_rn(__fadd_rn(s0, tr0), e);
            float v1 = __fadd_rn(__fadd_rn(s1, tr1), e);
            float v2 = __fadd_rn(__fadd_rn(s2, tr2), e);
            float v3 = __fadd_rn(__fadd_rn(s3, tr3), e);
            float best = v0; int bpi = 0;
            if (v1 > best) { best = v1; bpi = 1; }
            if (v2 > best) { best = v2; bpi = 2; }
            if (v3 > best) { best = v3; bpi = 3; }
            score = best;
            bp[s * 4 + t] = (unsigned char)bpi;
        }
        score = __fadd_rn(score, end_t[t]);
        float f0 = __shfl_sync(0xFu, score, 0);
        float f1 = __shfl_sync(0xFu, score, 1);
        float f2 = __shfl_sync(0xFu, score, 2);
        float f3 = __shfl_sync(0xFu, score, 3);
        __syncwarp(0xFu);
        if (t == 0) {
            float best = f0; int last = 0;
            if (f1 > best) { best = f1; last = 1; }
            if (f2 > best) { best = f2; last = 2; }
            if (f3 > best) { best = f3; last = 3; }
            int tag = last;
            path[SS - 1] = tag;
            for (int s = SS - 1; s >= 1; --s) {
                tag = bp[s * 4 + tag];
                path[s - 1] = tag;
            }
        }
    }
    __syncthreads();
    for (int i = tid; i < SS; i += 128)
        out[b * SS + i] = (float)path[i];
}

// =====================================================================
extern "C" void kernel_launch(void* const* d_in, const int* in_sizes, int n_in,
                              void* d_out, int out_size)
{
    const int*   sentences = (const int*)d_in[0];
    const float* embed   = (const float*)d_in[1];
    const float* w_ih_f  = (const float*)d_in[2];
    const float* w_hh_f  = (const float*)d_in[3];
    const float* b_ih_f  = (const float*)d_in[4];
    const float* b_hh_f  = (const float*)d_in[5];
    const float* w_ih_r  = (const float*)d_in[6];
    const float* w_hh_r  = (const float*)d_in[7];
    const float* b_ih_r  = (const float*)d_in[8];
    const float* b_hh_r  = (const float*)d_in[9];
    const float* w_out   = (const float*)d_in[10];
    const float* b_out   = (const float*)d_in[11];
    const float* start_t = (const float*)d_in[12];
    const float* end_t   = (const float*)d_in[13];
    const float* trans   = (const float*)d_in[14];

    // launch-shifters keep ncu's capture window on k2_lstm
    kdummy<<<1, 32>>>();
    kdummy<<<1, 32>>>();

    cudaFuncSetAttribute(k1_table, cudaFuncAttributeMaxDynamicSharedMemorySize, K1_SMEM);
    dim3 g1(8, 250);
    k1_table<<<g1, 256, K1_SMEM>>>(embed, w_ih_f, w_ih_r);

    cudaFuncSetAttribute(k2_lstm, cudaFuncAttributeMaxDynamicSharedMemorySize, K2_SMEM);
    k2_lstm<<<128, 256, K2_SMEM>>>(sentences, w_hh_f, w_hh_r,
                                   b_ih_f, b_hh_f, b_ih_r, b_hh_r);

    k3_emis<<<8192, 256>>>(w_out, b_out);
    k4_viterbi<<<64, 128>>>(start_t, end_t, trans, (float*)d_out);
}